// round 17
// baseline (speedup 1.0000x reference)
#include <cuda_runtime.h>
#include <cuda_bf16.h>
#include <math.h>
#include <cstdint>

#define NROWS 8192
#define DDIM  64
#define MARGIN 1.1f
#define EPS 1e-8f
#define TILE 128
#define NPREP 64
#define NWORKERS 296              // 2 CTAs/SM x 148 SMs
#define NUNITS 600                // 296x5 + 296x2 + 8x1 = 2080 tiles
#define ROWB 144
#define BUFB (TILE * ROWB)        // 18432 B
#define SMEM_TOTAL (4 * BUFB + 64)   // A0 A1 B0 B1

// Scratch (no allocs allowed).
__device__ __align__(16) __nv_bfloat16 g_xb[NROWS * DDIM];
__device__ double   g_accum;
__device__ unsigned g_prep_done;
__device__ unsigned g_done_ctr;
__device__ unsigned g_work;

__device__ __forceinline__ uint32_t smem_u32(const void* p) {
    uint32_t a;
    asm("{ .reg .u64 t; cvta.to.shared.u64 t, %1; cvt.u32.u64 %0, t; }"
        : "=r"(a) : "l"(p));
    return a;
}

__device__ __forceinline__ void ldsm_x4(uint32_t& r0, uint32_t& r1,
                                        uint32_t& r2, uint32_t& r3,
                                        uint32_t addr) {
    asm volatile("ldmatrix.sync.aligned.m8n8.x4.shared.b16 {%0,%1,%2,%3}, [%4];"
                 : "=r"(r0), "=r"(r1), "=r"(r2), "=r"(r3) : "r"(addr));
}

__device__ __forceinline__ void mma_16816(float* c, const uint32_t* a,
                                          uint32_t b0, uint32_t b1) {
    asm volatile(
        "mma.sync.aligned.m16n8k16.row.col.f32.bf16.bf16.f32 "
        "{%0,%1,%2,%3}, {%4,%5,%6,%7}, {%8,%9}, {%0,%1,%2,%3};"
        : "+f"(c[0]), "+f"(c[1]), "+f"(c[2]), "+f"(c[3])
        : "r"(a[0]), "r"(a[1]), "r"(a[2]), "r"(a[3]), "r"(b0), "r"(b1));
}

__device__ __forceinline__ void cpa16(uint32_t dst, const void* src) {
    asm volatile("cp.async.cg.shared.global [%0], [%1], 16;"
                 :: "r"(dst), "l"(src) : "memory");
}
#define CPA_COMMIT() asm volatile("cp.async.commit_group;" ::: "memory")
#define CPA_WAIT0()  asm volatile("cp.async.wait_group 0;" ::: "memory")

__device__ __forceinline__ void stage_tile(uint32_t dstb,
                                           const __nv_bfloat16* src, int tid) {
    const char* s = (const char*)src;
    #pragma unroll
    for (int r = 0; r < 4; r++) {
        int idx = tid + r * 256;
        int row = idx >> 3;
        int ch  = idx & 7;
        cpa16(dstb + row * ROWB + ch * 16, s + idx * 16);
    }
}

// Linear triangular tile id -> (bi, bj), bi <= bj.
__device__ __forceinline__ void tile_decode(int t, int& bi, int& bj) {
    int b = (int)((129.0f - sqrtf(16641.0f - 8.0f * (float)t)) * 0.5f);
    while (b * (129 - b) / 2 > t) b--;
    while ((b + 1) * (128 - b) / 2 <= t) b++;
    bi = b;
    bj = b + (t - b * (129 - b) / 2);
}

__device__ __forceinline__ void unit_decode(int u, int& s, int& n) {
    if (u < 296)      { s = u * 5;                n = 5; }
    else if (u < 592) { s = 1480 + (u - 296) * 2; n = 2; }
    else              { s = 2072 + (u - 592);     n = 1; }
}

// ---------------------------------------------------------------------------
// R16 base (guided schedule + early steal + double-buffered staging) with the
// warp-tile computed as TWO 32x32-col halves: all-k fragments per half, so
// half-1's ldsm+HMMA stream is independent of half-0's epilogue and the
// scalar pipes overlap the tensor pipe inside one warp.
// ---------------------------------------------------------------------------
__global__ __launch_bounds__(256, 2) void fused_kernel(
    const float* __restrict__ x, const int* __restrict__ cls,
    float* __restrict__ out) {

    extern __shared__ __align__(16) char dsm[];
    float* red   = (float*)(dsm + 4 * BUFB);
    int*   sunit = (int*)(red + 8);

    const int bid  = blockIdx.x;
    const int tid  = threadIdx.x;
    const int wid  = tid >> 5;
    const int lane = tid & 31;

    // ---------------- Phase 1: prep (normalize -> bf16), blocks 0..63 ------
    if (bid < NPREP) {
        int t    = bid * 256 + tid;
        int row  = t >> 1;
        int half = t & 1;
        const float4* xr = (const float4*)(x + (size_t)row * DDIM + half * 32);
        float4 v[8];
        #pragma unroll
        for (int i = 0; i < 8; i++) v[i] = xr[i];
        float s = 0.0f;
        #pragma unroll
        for (int i = 0; i < 8; i++)
            s += v[i].x * v[i].x + v[i].y * v[i].y +
                 v[i].z * v[i].z + v[i].w * v[i].w;
        s += __shfl_xor_sync(0xffffffffu, s, 1);
        float inv = 1.0f / fmaxf(sqrtf(s), EPS);
        __nv_bfloat16* dst = g_xb + (size_t)row * DDIM + half * 32;
        #pragma unroll
        for (int i = 0; i < 8; i++) {
            __nv_bfloat162 p0 = {__float2bfloat16(v[i].x * inv),
                                 __float2bfloat16(v[i].y * inv)};
            __nv_bfloat162 p1 = {__float2bfloat16(v[i].z * inv),
                                 __float2bfloat16(v[i].w * inv)};
            *(__nv_bfloat162*)(dst + i * 4)     = p0;
            *(__nv_bfloat162*)(dst + i * 4 + 2) = p1;
        }
        __syncthreads();
        if (tid == 0) { __threadfence(); atomicAdd(&g_prep_done, 1u); }
    }

    // ---------------- Device-wide wait for prep ----------------------------
    if (tid == 0) {
        unsigned v;
        do {
            asm volatile("ld.acquire.gpu.u32 %0, [%1];"
                         : "=r"(v) : "l"(&g_prep_done));
            if (v < (unsigned)NPREP) __nanosleep(64);
        } while (v < (unsigned)NPREP);
    }
    __syncthreads();

    const int wm = wid & 3;
    const int wn = wid >> 2;
    const uint32_t aBufu[2] = { smem_u32(dsm), smem_u32(dsm + BUFB) };
    const uint32_t bBufu[2] = { smem_u32(dsm + 2 * BUFB),
                                smem_u32(dsm + 3 * BUFB) };
    const uint32_t a_lane_off =
        (uint32_t)((wm * 32 + (lane & 15)) * ROWB + ((lane >> 4) << 4));
    const uint32_t b_lane_off =
        (uint32_t)((wn * 64 + (lane & 7) + ((lane >> 4) << 3)) * ROWB +
                   (((lane >> 3) & 1) << 4));
    const float MC = MARGIN - 1.0f;
    const int quad = lane >> 2;
    const int tq   = lane & 3;

    int curAbi = -1;
    int aCur   = 0;
    int wcnt   = 0;
    float lsum = 0.0f;

    // ---------------- Acquire first unit + stage its first tile ------------
    if (tid == 0) *sunit = (int)atomicAdd(&g_work, 1u);
    __syncthreads();
    int u = *sunit;
    bool active = (u < NUNITS);
    int s = 0, n = 0, i = 0, cbi = 0, cbj = 0;
    if (active) {
        unit_decode(u, s, n);
        tile_decode(s, cbi, cbj);
        if (cbi != curAbi)
            stage_tile(aBufu[aCur ^ 1], g_xb + (size_t)cbi * TILE * DDIM, tid);
        stage_tile(bBufu[0], g_xb + (size_t)cbj * TILE * DDIM, tid);
        CPA_COMMIT();
    }

    // ==================== Persistent tile stream ============================
    while (active) {
        const bool last = (i == n - 1);
        if (tid == 0 && last) *sunit = (int)atomicAdd(&g_work, 1u);
        CPA_WAIT0();
        __syncthreads();            // tile data ready + sunit visible
        if (cbi != curAbi) { aCur ^= 1; curAbi = cbi; }

        // ---- determine & stage next tile (possibly from the NEXT unit) ----
        int nbi = -1, nbj = -1;
        bool havenext = false;
        if (!last) {
            tile_decode(s + i + 1, nbi, nbj);
            havenext = true;
        } else {
            int u2 = *sunit;
            if (u2 < NUNITS) {
                unit_decode(u2, s, n);
                i = -1;             // incremented to 0 below
                tile_decode(s, nbi, nbj);
                havenext = true;
            }
        }
        if (havenext) {
            if (nbi != curAbi)
                stage_tile(aBufu[aCur ^ 1],
                           g_xb + (size_t)nbi * TILE * DDIM, tid);
            stage_tile(bBufu[(wcnt + 1) & 1],
                       g_xb + (size_t)nbj * TILE * DDIM, tid);
            CPA_COMMIT();
        }

        // ---- row classes for this tile (L1-resident) ----
        const int* cr = cls + cbi * TILE + wm * 32 + quad;
        const int ci00 = __ldg(cr);      const int ci01 = __ldg(cr + 8);
        const int ci10 = __ldg(cr + 16); const int ci11 = __ldg(cr + 24);

        const uint32_t a_base = aBufu[aCur] + a_lane_off;
        const uint32_t b_base = bBufu[wcnt & 1] + b_lane_off;

        // ---- A fragments: all k, loaded once per tile (32 regs) ----
        uint32_t aR[4][2][4];
        #pragma unroll
        for (int k = 0; k < 4; k++)
            #pragma unroll
            for (int m = 0; m < 2; m++)
                ldsm_x4(aR[k][m][0], aR[k][m][1], aR[k][m][2], aR[k][m][3],
                        a_base + m * 16 * ROWB + k * 32);

        // ---- two 32-column halves; half h+1's MMA overlaps half h's epi ----
        float l0 = 0.0f, l1 = 0.0f;
        #pragma unroll
        for (int h = 0; h < 2; h++) {
            uint32_t bR[4][4][2];            // [k][nn][frag], 32 regs
            #pragma unroll
            for (int k = 0; k < 4; k++)
                #pragma unroll
                for (int q = 0; q < 2; q++) {
                    uint32_t r0, r1, r2, r3;
                    ldsm_x4(r0, r1, r2, r3,
                            b_base + (h * 2 + q) * 16 * ROWB + k * 32);
                    bR[k][q * 2 + 0][0] = r0; bR[k][q * 2 + 0][1] = r1;
                    bR[k][q * 2 + 1][0] = r2; bR[k][q * 2 + 1][1] = r3;
                }

            float c[2][4][4];
            #pragma unroll
            for (int m = 0; m < 2; m++)
                #pragma unroll
                for (int nn = 0; nn < 4; nn++)
                    #pragma unroll
                    for (int e = 0; e < 4; e++) c[m][nn][e] = 0.0f;

            #pragma unroll
            for (int k = 0; k < 4; k++)
                #pragma unroll
                for (int m = 0; m < 2; m++)
                    #pragma unroll
                    for (int nn = 0; nn < 4; nn++)
                        mma_16816(c[m][nn], aR[k][m],
                                  bR[k][nn][0], bR[k][nn][1]);

            // ---- epilogue of this half ----
            const int* cj = cls + cbj * TILE + wn * 64 + h * 32 + tq * 2;
            #pragma unroll
            for (int m = 0; m < 2; m++) {
                const int ci0 = m ? ci10 : ci00;
                const int ci1 = m ? ci11 : ci01;
                #pragma unroll
                for (int nn = 0; nn < 4; nn++) {
                    const int2 cjp = __ldg((const int2*)(cj + nn * 8));
                    float v0 = c[m][nn][0], v1 = c[m][nn][1];
                    float v2 = c[m][nn][2], v3 = c[m][nn][3];
                    l0 += (ci0 == cjp.x) ? (1.0f - v0) : fmaxf(v0 + MC, 0.0f);
                    l1 += (ci0 == cjp.y) ? (1.0f - v1) : fmaxf(v1 + MC, 0.0f);
                    l0 += (ci1 == cjp.x) ? (1.0f - v2) : fmaxf(v2 + MC, 0.0f);
                    l1 += (ci1 == cjp.y) ? (1.0f - v3) : fmaxf(v3 + MC, 0.0f);
                }
            }
        }
        float tl = l0 + l1;
        lsum += (cbi == cbj) ? tl : 2.0f * tl;

        wcnt++;
        if (!havenext) break;
        cbi = nbi; cbj = nbj; i++;
    }

    // ---------------- One reduce + atomic per block --------------------------
    #pragma unroll
    for (int o = 16; o; o >>= 1) lsum += __shfl_xor_sync(0xffffffffu, lsum, o);
    if (lane == 0) red[wid] = lsum;
    __syncthreads();
    if (tid == 0) {
        float tt = 0.0f;
        #pragma unroll
        for (int w = 0; w < 8; w++) tt += red[w];
        atomicAdd(&g_accum, (double)tt);
        __threadfence();
        unsigned old = atomicAdd(&g_done_ctr, 1u);
        if (old == (unsigned)(NWORKERS - 1)) {
            double a = atomicAdd(&g_accum, 0.0);
            out[0] = (float)(a / ((double)NROWS * (double)NROWS));
            g_accum     = 0.0;
            g_done_ctr  = 0u;
            g_prep_done = 0u;
            g_work      = 0u;
        }
    }
}

extern "C" void kernel_launch(void* const* d_in, const int* in_sizes, int n_in,
                              void* d_out, int out_size) {
    const float* bottleneck = (const float*)d_in[0];
    const int*   class_map  = (const int*)d_in[1];
    float*       out        = (float*)d_out;

    cudaFuncSetAttribute(fused_kernel,
                         cudaFuncAttributeMaxDynamicSharedMemorySize,
                         SMEM_TOTAL);
    fused_kernel<<<NWORKERS, 256, SMEM_TOTAL>>>(bottleneck, class_map, out);
}